// round 11
// baseline (speedup 1.0000x reference)
#include <cuda_runtime.h>
#include <float.h>
#include <math.h>

// Problem shape: logits (2048, 3, 32000) fp32, targets (2048, 4) int64-or-int32.
// Output: scalar fp32 ECE.
#define NROWS 6144      // 2048 * 3
#define NV    32000
#define NV4   8000      // NV / 4
#define TPB   256
#define NBATCH 2048

// Intermediate per-row results (static device scratch — no allocation).
__device__ float g_conf[NROWS];
__device__ int   g_pred[NROWS];

// Online softmax-max update: maintains running max m, running sum of exp(x-m),
// and argmax (first occurrence). Single exp per element via exp(-|x-m|).
__device__ __forceinline__ void upd(float x, int idx, float& m, float& s, int& am) {
    float d = x - m;
    float e = __expf(-fabsf(d));   // exp(m-x) if x>m else exp(x-m)
    if (d > 0.0f) {                // strictly greater: first occurrence wins
        s  = fmaf(s, e, 1.0f);     // rescale old sum, add exp(0)=1 for new max
        m  = x;
        am = idx;
    } else {
        s += e;
    }
}

// Merge two (max, sum, argmax) partials. Tie on max -> lower index (argmax
// first-occurrence semantics). Safe for padding lanes with m=-FLT_MAX, s=0.
__device__ __forceinline__ void merge(float& m, float& s, int& am,
                                      float om, float os, int oam) {
    float nm = fmaxf(m, om);
    s = s * __expf(m - nm) + os * __expf(om - nm);
    if (om > m || (om == m && oam < am)) am = oam;
    m = nm;
}

__global__ __launch_bounds__(TPB) void softmax_rows(const float* __restrict__ logits) {
    const int row = blockIdx.x;
    const float4* __restrict__ p =
        reinterpret_cast<const float4*>(logits) + (size_t)row * NV4;

    // Four independent accumulator triples (one per float4 lane) to cut the
    // per-thread dependent chain (which includes a 16-cycle MUFU exp) by 4x.
    float m0 = -FLT_MAX, m1 = -FLT_MAX, m2 = -FLT_MAX, m3 = -FLT_MAX;
    float s0 = 0.f, s1 = 0.f, s2 = 0.f, s3 = 0.f;
    int   a0 = 0, a1 = 1, a2 = 2, a3 = 3;

    #pragma unroll 4
    for (int i = threadIdx.x; i < NV4; i += TPB) {
        float4 v = __ldg(p + i);
        int b = i << 2;
        upd(v.x, b,     m0, s0, a0);
        upd(v.y, b + 1, m1, s1, a1);
        upd(v.z, b + 2, m2, s2, a2);
        upd(v.w, b + 3, m3, s3, a3);
    }

    // Combine the four lane accumulators (tie-break handled inside merge).
    merge(m0, s0, a0, m1, s1, a1);
    merge(m2, s2, a2, m3, s3, a3);
    merge(m0, s0, a0, m2, s2, a2);
    float m = m0, s = s0;
    int am = a0;

    const unsigned FULL = 0xffffffffu;
    #pragma unroll
    for (int off = 16; off; off >>= 1) {
        float om  = __shfl_xor_sync(FULL, m,  off);
        float os  = __shfl_xor_sync(FULL, s,  off);
        int   oam = __shfl_xor_sync(FULL, am, off);
        merge(m, s, am, om, os, oam);
    }

    __shared__ float smx[TPB / 32];
    __shared__ float ssm[TPB / 32];
    __shared__ int   sam[TPB / 32];
    const int wid = threadIdx.x >> 5;
    const int lid = threadIdx.x & 31;
    if (lid == 0) { smx[wid] = m; ssm[wid] = s; sam[wid] = am; }
    __syncthreads();

    if (wid == 0) {
        const int NW = TPB / 32;
        m  = (lid < NW) ? smx[lid] : -FLT_MAX;
        s  = (lid < NW) ? ssm[lid] : 0.0f;
        am = (lid < NW) ? sam[lid] : 0x7fffffff;
        #pragma unroll
        for (int off = NW >> 1; off; off >>= 1) {
            float om  = __shfl_xor_sync(FULL, m,  off);
            float os  = __shfl_xor_sync(FULL, s,  off);
            int   oam = __shfl_xor_sync(FULL, am, off);
            merge(m, s, am, om, os, oam);
        }
        if (lid == 0) {
            g_conf[row] = 1.0f / s;   // max softmax prob = exp(m-m)/sum = 1/sum
            g_pred[row] = am;
        }
    }
}

// Epilogue: per-batch confidence product + accuracy, 15-bin ECE.
// per_bin = |avg_conf - avg_acc| * prop_in_bin == |conf_sum - acc_sum| / n
// (exact when count>0; zero-sum bins contribute 0 either way).
__global__ void ece_finish(const void* __restrict__ tptr, float* __restrict__ out) {
    __shared__ float sc[15];
    __shared__ float sa[15];
    __shared__ int   s_is64;
    const int t = threadIdx.x;
    if (t < 15) { sc[t] = 0.0f; sa[t] = 0.0f; }
    if (t == 0) s_is64 = 1;
    __syncthreads();

    // Detect int64 vs int32 targets layout. Read only the first 8192 int32
    // words (32 KB) — safe under both interpretations. int64 little-endian
    // values < 32000 have all-zero high words at odd int32 positions.
    const int* t32 = (const int*)tptr;
    for (int i = t; i < 4096; i += blockDim.x)
        if (t32[2 * i + 1] != 0) s_is64 = 0;   // benign race: only writes 0
    __syncthreads();
    const bool is64 = (s_is64 != 0);
    const long long* t64 = (const long long*)tptr;

    for (int b = t; b < NBATCH; b += blockDim.x) {
        float c = g_conf[b * 3] * g_conf[b * 3 + 1] * g_conf[b * 3 + 2];
        int hits = 0;
        #pragma unroll
        for (int j = 0; j < 3; j++) {
            int k = b * 4 + j + 1;            // targets[:, 1:4]
            int tv = is64 ? (int)t64[k] : t32[k];
            hits += (g_pred[b * 3 + j] == tv);
        }
        float a = (float)hits * (1.0f / 3.0f);

        // bin membership: conf > i/15 && conf <= (i+1)/15  ->  ceil(c*15)-1
        int bin = (int)ceilf(c * 15.0f) - 1;
        bin = bin < 0 ? 0 : (bin > 14 ? 14 : bin);
        atomicAdd(&sc[bin], c);
        atomicAdd(&sa[bin], a);
    }
    __syncthreads();

    if (t == 0) {
        float ece = 0.0f;
        #pragma unroll
        for (int i = 0; i < 15; i++) ece += fabsf(sc[i] - sa[i]);
        out[0] = ece * (1.0f / 2048.0f);
    }
}

extern "C" void kernel_launch(void* const* d_in, const int* in_sizes, int n_in,
                              void* d_out, int out_size) {
    const float* logits = (const float*)d_in[0];
    softmax_rows<<<NROWS, TPB>>>(logits);
    ece_finish<<<1, 256>>>(d_in[1], (float*)d_out);
}

// round 16
// speedup vs baseline: 1.3995x; 1.3995x over previous
#include <cuda_runtime.h>
#include <float.h>
#include <math.h>

// Problem shape: logits (2048, 3, 32000) fp32, targets (2048, 4) int64-or-int32.
// Output: scalar fp32 ECE.
#define NROWS 6144      // 2048 * 3
#define NV    32000
#define NV4   8000      // NV / 4
#define TPB   256
#define NBATCH 2048

// Intermediate per-row results (static device scratch — no allocation).
__device__ float g_conf[NROWS];
__device__ int   g_pred[NROWS];

// Online softmax-max update: maintains running max m, running sum of exp(x-m),
// and argmax (first occurrence). Single exp per element via exp(-|x-m|).
__device__ __forceinline__ void upd(float x, int idx, float& m, float& s, int& am) {
    float d = x - m;
    float e = __expf(-fabsf(d));   // exp(m-x) if x>m else exp(x-m)
    if (d > 0.0f) {                // strictly greater: first occurrence wins
        s  = fmaf(s, e, 1.0f);     // rescale old sum, add exp(0)=1 for new max
        m  = x;
        am = idx;
    } else {
        s += e;
    }
}

// Merge two (max, sum, argmax) partials. Tie on max -> lower index (argmax
// first-occurrence semantics). Safe for padding lanes with m=-FLT_MAX, s=0.
__device__ __forceinline__ void merge(float& m, float& s, int& am,
                                      float om, float os, int oam) {
    float nm = fmaxf(m, om);
    s = s * __expf(m - nm) + os * __expf(om - nm);
    if (om > m || (om == m && oam < am)) am = oam;
    m = nm;
}

__global__ __launch_bounds__(TPB) void softmax_rows(const float* __restrict__ logits) {
    const int row = blockIdx.x;
    const float4* __restrict__ p =
        reinterpret_cast<const float4*>(logits) + (size_t)row * NV4;

    // Four independent accumulator triples (one per float4 lane) to cut the
    // per-thread dependent chain (which includes a 16-cycle MUFU exp) by 4x.
    float m0 = -FLT_MAX, m1 = -FLT_MAX, m2 = -FLT_MAX, m3 = -FLT_MAX;
    float s0 = 0.f, s1 = 0.f, s2 = 0.f, s3 = 0.f;
    int   a0 = 0, a1 = 1, a2 = 2, a3 = 3;

    #pragma unroll 4
    for (int i = threadIdx.x; i < NV4; i += TPB) {
        float4 v = __ldg(p + i);
        int b = i << 2;
        upd(v.x, b,     m0, s0, a0);
        upd(v.y, b + 1, m1, s1, a1);
        upd(v.z, b + 2, m2, s2, a2);
        upd(v.w, b + 3, m3, s3, a3);
    }

    // Combine the four lane accumulators (tie-break handled inside merge).
    merge(m0, s0, a0, m1, s1, a1);
    merge(m2, s2, a2, m3, s3, a3);
    merge(m0, s0, a0, m2, s2, a2);
    float m = m0, s = s0;
    int am = a0;

    const unsigned FULL = 0xffffffffu;
    #pragma unroll
    for (int off = 16; off; off >>= 1) {
        float om  = __shfl_xor_sync(FULL, m,  off);
        float os  = __shfl_xor_sync(FULL, s,  off);
        int   oam = __shfl_xor_sync(FULL, am, off);
        merge(m, s, am, om, os, oam);
    }

    __shared__ float smx[TPB / 32];
    __shared__ float ssm[TPB / 32];
    __shared__ int   sam[TPB / 32];
    const int wid = threadIdx.x >> 5;
    const int lid = threadIdx.x & 31;
    if (lid == 0) { smx[wid] = m; ssm[wid] = s; sam[wid] = am; }
    __syncthreads();

    if (wid == 0) {
        const int NW = TPB / 32;
        m  = (lid < NW) ? smx[lid] : -FLT_MAX;
        s  = (lid < NW) ? ssm[lid] : 0.0f;
        am = (lid < NW) ? sam[lid] : 0x7fffffff;
        #pragma unroll
        for (int off = NW >> 1; off; off >>= 1) {
            float om  = __shfl_xor_sync(FULL, m,  off);
            float os  = __shfl_xor_sync(FULL, s,  off);
            int   oam = __shfl_xor_sync(FULL, am, off);
            merge(m, s, am, om, os, oam);
        }
        if (lid == 0) {
            g_conf[row] = 1.0f / s;   // max softmax prob = exp(m-m)/sum = 1/sum
            g_pred[row] = am;
        }
    }
}

// Epilogue: per-batch confidence product + accuracy, 15-bin ECE.
// per_bin = |avg_conf - avg_acc| * prop_in_bin == |conf_sum - acc_sum| / n
// (exact when count>0; zero-sum bins contribute 0 either way).
//
// NO shared atomics: with this data every sample lands in the same bin, and
// same-address ATOMS serialize (~32 cyc/warp) -> measured 77us. Instead each
// thread keeps register-resident 15-bin partials (unrolled predicated adds),
// reduced via warp shuffles + a tiny smem tree.
__global__ __launch_bounds__(256) void ece_finish(const void* __restrict__ tptr,
                                                  float* __restrict__ out) {
    __shared__ int s_is64;
    const int t   = threadIdx.x;
    const int wid = t >> 5;
    const int lid = t & 31;
    if (t == 0) s_is64 = 1;
    __syncthreads();

    // Detect int64 vs int32 targets layout. Read only the first 8192 int32
    // words (32 KB) — safe under both interpretations. int64 little-endian
    // values < 32000 have all-zero high words at odd int32 positions.
    const int* t32 = (const int*)tptr;
    int any_hi = 0;
    for (int i = t; i < 4096; i += 256) any_hi |= t32[2 * i + 1];
    if (any_hi != 0) s_is64 = 0;   // benign race: only writes 0
    __syncthreads();
    const bool is64 = (s_is64 != 0);
    const long long* t64 = (const long long*)tptr;

    // Register-resident per-thread bin partials.
    float lc[15], la[15];
    #pragma unroll
    for (int i = 0; i < 15; i++) { lc[i] = 0.0f; la[i] = 0.0f; }

    for (int b = t; b < NBATCH; b += 256) {
        // Hoist all global loads (independent -> MLP) before use.
        float c0 = g_conf[b * 3], c1 = g_conf[b * 3 + 1], c2 = g_conf[b * 3 + 2];
        int   p0 = g_pred[b * 3], p1 = g_pred[b * 3 + 1], p2 = g_pred[b * 3 + 2];
        int tv0, tv1, tv2;
        if (is64) {
            tv0 = (int)t64[b * 4 + 1]; tv1 = (int)t64[b * 4 + 2]; tv2 = (int)t64[b * 4 + 3];
        } else {
            tv0 = t32[b * 4 + 1]; tv1 = t32[b * 4 + 2]; tv2 = t32[b * 4 + 3];
        }

        float c = c0 * c1 * c2;
        int hits = (p0 == tv0) + (p1 == tv1) + (p2 == tv2);
        float a = (float)hits * (1.0f / 3.0f);

        // bin membership: conf > i/15 && conf <= (i+1)/15  ->  ceil(c*15)-1
        int bin = (int)ceilf(c * 15.0f) - 1;
        bin = bin < 0 ? 0 : (bin > 14 ? 14 : bin);

        // Unrolled predicated accumulation -> stays in registers, no atomics.
        #pragma unroll
        for (int i = 0; i < 15; i++) {
            if (i == bin) { lc[i] += c; la[i] += a; }
        }
    }

    // Warp-level reduction of the 30 partials.
    const unsigned FULL = 0xffffffffu;
    #pragma unroll
    for (int i = 0; i < 15; i++) {
        #pragma unroll
        for (int off = 16; off; off >>= 1) {
            lc[i] += __shfl_xor_sync(FULL, lc[i], off);
            la[i] += __shfl_xor_sync(FULL, la[i], off);
        }
    }

    // Cross-warp reduction: lane 0 of each of the 8 warps deposits partials.
    __shared__ float wc[8][15];
    __shared__ float wa[8][15];
    if (lid == 0) {
        #pragma unroll
        for (int i = 0; i < 15; i++) { wc[wid][i] = lc[i]; wa[wid][i] = la[i]; }
    }
    __syncthreads();

    if (t == 0) {
        float ece = 0.0f;
        #pragma unroll
        for (int i = 0; i < 15; i++) {
            float cs = 0.0f, as = 0.0f;
            #pragma unroll
            for (int w = 0; w < 8; w++) { cs += wc[w][i]; as += wa[w][i]; }
            ece += fabsf(cs - as);
        }
        out[0] = ece * (1.0f / 2048.0f);
    }
}

extern "C" void kernel_launch(void* const* d_in, const int* in_sizes, int n_in,
                              void* d_out, int out_size) {
    const float* logits = (const float*)d_in[0];
    softmax_rows<<<NROWS, TPB>>>(logits);
    ece_finish<<<1, 256>>>(d_in[1], (float*)d_out);
}